// round 4
// baseline (speedup 1.0000x reference)
#include <cuda_runtime.h>
#include <cuda_fp16.h>
#include <cstdint>

// Problem constants
#define D_IN   256
#define D_OUT  256
#define BATCH  512
#define KNOTS  64
#define INV_H  15.75f          // 63/4, exact in fp32
#define H_VAL  (4.0f/63.0f)

#define NCHUNK 32              // din chunks
#define DCHUNK 8               // din per chunk
#define TB     256             // batch rows per block

// tile: 64 knots x 32 pairs of uint4 {y2(l), hm2(l), y2(l+32), hm2(l+32)} = 32KB
#define TILE_U4 (64*32)        // 2048 uint4

// smem: 2 tile buffers (64KB) + cw (TB*DCHUNK uint4 = 32KB) = 96KB
#define SMEM_BYTES (2*TILE_U4*16 + TB*DCHUNK*16)

// Scratch (device globals; no allocation)
// g_pack2[(din*4+dx)*2048 + j*32 + p] = {y2(p,j), hm2(p,j), y2(p+32,j), hm2(p+32,j)}
__device__ uint4 g_pack2[(size_t)D_IN * 4 * TILE_U4];           // 33.5 MB
__device__ float g_partial[(size_t)NCHUNK * BATCH * D_OUT];     // 16 MB

// ---------------------------------------------------------------------------
// Kernel A: PCHIP slopes + half4 packing into the transposed pair layout.
// Block = one (din, dout-tile-of-64): reads 16KB contiguous, writes 32KB
// contiguous. Warp-per-spline shuffle math, smem staging for the transpose.
// ---------------------------------------------------------------------------
__device__ __forceinline__ float pchip_interior(float d0, float d1) {
    float p   = d0 * d1;
    float den = d0 + d1;
    float m   = __fdividef(2.0f * p, den);
    bool  ok  = (p > 0.0f) && (fabsf(den) >= 1e-12f);
    return ok ? m : 0.0f;
}
__device__ __forceinline__ float pchip_endpoint(float d_near, float d_far) {
    float m = 1.5f * d_near - 0.5f * d_far;
    m = (m * d_near <= 0.0f) ? 0.0f : m;
    bool clamp3 = (d_near * d_far < 0.0f) && (fabsf(m) > 3.0f * fabsf(d_near));
    return clamp3 ? 3.0f * d_near : m;
}

__global__ void __launch_bounds__(256) pchip_pack_kernel(const float* __restrict__ y) {
    // staging: 64 rows (j) x 66 uint2 (64 data + 2 pad)
    __shared__ uint2 st[64 * 66];

    const int tid  = threadIdx.x;
    const int w    = tid >> 5;
    const int lane = tid & 31;
    const int bx   = blockIdx.x;          // (din*4 + dx)

    const float* src = y + (size_t)bx * 4096;   // 64 splines x 64 knots

#pragma unroll
    for (int k = 0; k < 8; ++k) {
        const int s = w * 8 + k;                 // local dout (spline) 0..63
        float2 v = ((const float2*)(src + s * KNOTS))[lane];
        float y0 = v.x, y1 = v.y;                               // y[2l], y[2l+1]
        float y2 = __shfl_down_sync(0xFFFFFFFFu, y0, 1);        // y[2l+2]

        float da = (y1 - y0) * INV_H;                           // delta[2l]
        float db = (y2 - y1) * INV_H;                           // delta[2l+1]
        float dprev = __shfl_up_sync(0xFFFFFFFFu, db, 1);       // delta[2l-1]

        float m_e = (lane == 0)  ? pchip_endpoint(da, db)
                                 : pchip_interior(dprev, da);
        float m_o = (lane == 31) ? pchip_endpoint(da, dprev)
                                 : pchip_interior(da, db);

        float he = H_VAL * m_e, ho = H_VAL * m_o;
        float he_next = __shfl_down_sync(0xFFFFFFFFu, he, 1);

        __half2 ya = __floats2half2_rn(y0, y1);
        __half2 ha = __floats2half2_rn(he, ho);
        __half2 yb = __floats2half2_rn(y1, (lane == 31) ? y1 : y2);
        __half2 hb = __floats2half2_rn(ho, (lane == 31) ? ho : he_next);

        const int p  = s & 31;
        const int hi = s >> 5;
        uint2 e0, e1;
        e0.x = *reinterpret_cast<unsigned*>(&ya);
        e0.y = *reinterpret_cast<unsigned*>(&ha);
        e1.x = *reinterpret_cast<unsigned*>(&yb);
        e1.y = *reinterpret_cast<unsigned*>(&hb);
        st[(2 * lane)     * 66 + 2 * p + hi] = e0;   // knot 2l
        st[(2 * lane + 1) * 66 + 2 * p + hi] = e1;   // knot 2l+1
    }
    __syncthreads();

    // cooperative coalesced store: 2048 uint4
    uint4* dst = g_pack2 + (size_t)bx * TILE_U4;
    const uint4* st4 = (const uint4*)st;             // row pitch 33 uint4 (66 uint2, 16B-aligned)
#pragma unroll
    for (int g = tid; g < TILE_U4; g += 256) {
        int j = g >> 5, p = g & 31;
        dst[g] = st4[j * 33 + p];
    }
}

// ---------------------------------------------------------------------------
// Kernel B: main gather-accumulate.
// Grid (4 dout tiles, 2 b tiles, 32 din chunks) = 256 blocks, 256 threads.
// Warp w owns b rows [w*32, w*32+32); lane l owns douts l and l+32 (local).
// Per (b,din): 1 broadcast LDS.128 (weights+idx) + 1 gather LDS.128 (both rows).
// ---------------------------------------------------------------------------
__device__ __forceinline__ void cp_async16(void* dst, const void* src) {
    unsigned sa = (unsigned)__cvta_generic_to_shared(dst);
    asm volatile("cp.async.cg.shared.global [%0], [%1], 16;\n" :: "r"(sa), "l"(src));
}
__device__ __forceinline__ __half2 u2h(unsigned u) {
    return *reinterpret_cast<__half2*>(&u);
}

__global__ void __launch_bounds__(256, 2) kan_main_kernel(const float* __restrict__ x) {
    extern __shared__ uint4 sm4[];
    uint4* tile = sm4;                       // 2 x TILE_U4
    uint4* cw   = sm4 + 2 * TILE_U4;         // TB*DCHUNK: {wy, wh, idx, 0}

    const int dx  = blockIdx.x;   // dout tile (0..3)
    const int by  = blockIdx.y;   // b tile    (0..1)
    const int ch  = blockIdx.z;   // din chunk (0..31)
    const int tid = threadIdx.x;

    // ---- hermite weights + idx, combined 16B records ----
    for (int i = tid; i < TB * DCHUNK; i += 256) {
        int bb = i >> 3, dl = i & 7;
        float xv = x[(by * TB + bb) * D_IN + ch * DCHUNK + dl];
        xv = fminf(fmaxf(xv, -2.0f), 2.0f);
        float tt = (xv + 2.0f) * INV_H;
        int idx = (int)floorf(tt);
        if (idx > KNOTS - 2) idx = KNOTS - 2;
        if (idx < 0) idx = 0;
        float u  = tt - (float)idx;
        float u2 = u * u, u3 = u2 * u;
        float h00 = 2.0f * u3 - 3.0f * u2 + 1.0f;
        float h10 = u3 - 2.0f * u2 + u;
        float h01 = 3.0f * u2 - 2.0f * u3;
        float h11 = u3 - u2;
        __half2 wy = __floats2half2_rn(h00, h01);
        __half2 wh = __floats2half2_rn(h10, h11);
        uint4 r;
        r.x = *reinterpret_cast<unsigned*>(&wy);
        r.y = *reinterpret_cast<unsigned*>(&wh);
        r.z = (unsigned)idx;
        r.w = 0;
        cw[i] = r;
    }

    const int w = tid >> 5, l = tid & 31;
    float acc0[32], acc1[32];
#pragma unroll
    for (int bb = 0; bb < 32; ++bb) { acc0[bb] = 0.0f; acc1[bb] = 0.0f; }

    auto issue_copy = [&](int d, int st) {
        const uint4* src = g_pack2 + ((size_t)(ch * DCHUNK + d) * 4 + dx) * TILE_U4;
        uint4* dst = tile + st * TILE_U4;
#pragma unroll
        for (int j = tid; j < TILE_U4; j += 256) cp_async16(dst + j, src + j);
    };

    issue_copy(0, 0);
    asm volatile("cp.async.commit_group;\n" ::: "memory");

    for (int d = 0; d < DCHUNK; ++d) {
        const int st = d & 1;
        if (d < DCHUNK - 1) {
            issue_copy(d + 1, st ^ 1);
            asm volatile("cp.async.commit_group;\n" ::: "memory");
            asm volatile("cp.async.wait_group 1;\n" ::: "memory");
        } else {
            asm volatile("cp.async.wait_group 0;\n" ::: "memory");
        }
        __syncthreads();

        const uint4* tl = tile + st * TILE_U4 + l;     // + idx*32 per gather
        const int base = (w * 32) * DCHUNK + d;

#pragma unroll
        for (int bb = 0; bb < 32; ++bb) {
            uint4 r = cw[base + bb * DCHUNK];          // broadcast LDS.128
            __half2 wy = u2h(r.x), wh = u2h(r.y);
            uint4 g = tl[(int)r.z * 32];               // gather LDS.128 (both rows)

            __half2 p0 = __hfma2(wh, u2h(g.y), __hmul2(wy, u2h(g.x)));
            __half2 p1 = __hfma2(wh, u2h(g.w), __hmul2(wy, u2h(g.z)));

            acc0[bb] += __half2float(__hadd(__low2half(p0), __high2half(p0)));
            acc1[bb] += __half2float(__hadd(__low2half(p1), __high2half(p1)));
        }
        __syncthreads();
    }

    // ---- write partials ----
    float* P = g_partial + ((size_t)ch * BATCH + by * TB + w * 32) * D_OUT + dx * 64;
#pragma unroll
    for (int bb = 0; bb < 32; ++bb) {
        P[bb * D_OUT + l]      = acc0[bb];
        P[bb * D_OUT + l + 32] = acc1[bb];
    }
}

// ---------------------------------------------------------------------------
// Kernel C: reduce 32 partials + bias
// ---------------------------------------------------------------------------
__global__ void __launch_bounds__(256) reduce_kernel(
        const float* __restrict__ bias, float* __restrict__ out) {
    int i = blockIdx.x * 256 + threadIdx.x;            // float4 index
    const float4* P = (const float4*)g_partial;
    float4 s = ((const float4*)bias)[i & 63];
#pragma unroll
    for (int c = 0; c < NCHUNK; ++c) {
        float4 p = P[(size_t)c * (BATCH * D_OUT / 4) + i];
        s.x += p.x; s.y += p.y; s.z += p.z; s.w += p.w;
    }
    ((float4*)out)[i] = s;
}

// ---------------------------------------------------------------------------
extern "C" void kernel_launch(void* const* d_in, const int* in_sizes, int n_in,
                              void* d_out, int out_size) {
    const float* x    = (const float*)d_in[0];
    const float* y    = (const float*)d_in[1];
    const float* bias = (const float*)d_in[2];
    float* out = (float*)d_out;

    cudaFuncSetAttribute(kan_main_kernel,
                         cudaFuncAttributeMaxDynamicSharedMemorySize, SMEM_BYTES);

    pchip_pack_kernel<<<D_IN * 4, 256>>>(y);
    kan_main_kernel<<<dim3(4, 2, NCHUNK), 256, SMEM_BYTES>>>(x);
    reduce_kernel<<<(BATCH * D_OUT / 4) / 256, 256>>>(bias, out);
}

// round 5
// speedup vs baseline: 1.0525x; 1.0525x over previous
#include <cuda_runtime.h>
#include <cuda_fp16.h>
#include <cstdint>

// Problem constants
#define D_IN   256
#define D_OUT  256
#define BATCH  512
#define KNOTS  64
#define INV_H  15.75f          // 63/4, exact in fp32
#define H_VAL  (4.0f/63.0f)

#define NCHUNK 32              // din chunks
#define DCHUNK 8               // din per chunk
#define TB     256             // batch rows per block

// tile: 64 knots x 32 pairs of uint4 {y2(l), hm2(l), y2(l+32), hm2(l+32)} = 32KB
#define TILE_U4 (64*32)        // 2048 uint4

// smem for kernel B: 2 tile buffers (64KB) + cw (TB*DCHUNK uint4 = 32KB) = 96KB
#define SMEM_BYTES (2*TILE_U4*16 + TB*DCHUNK*16)

// Scratch (device globals; no allocation)
// g_pack2[(din*4+dx)*2048 + j*32 + p] = {y2(p,j), hm2(p,j), y2(p+32,j), hm2(p+32,j)}
__device__ uint4 g_pack2[(size_t)D_IN * 4 * TILE_U4];           // 33.5 MB
__device__ float g_partial[(size_t)NCHUNK * BATCH * D_OUT];     // 16 MB

// ---------------------------------------------------------------------------
// PCHIP slope helpers (branch-free)
// ---------------------------------------------------------------------------
__device__ __forceinline__ float pchip_interior(float d0, float d1) {
    float p   = d0 * d1;
    float den = d0 + d1;
    float m   = __fdividef(2.0f * p, den);
    bool  ok  = (p > 0.0f) && (fabsf(den) >= 1e-12f);
    return ok ? m : 0.0f;
}
__device__ __forceinline__ float pchip_endpoint(float d_near, float d_far) {
    float m = 1.5f * d_near - 0.5f * d_far;
    m = (m * d_near <= 0.0f) ? 0.0f : m;
    bool clamp3 = (d_near * d_far < 0.0f) && (fabsf(m) > 3.0f * fabsf(d_near));
    return clamp3 ? 3.0f * d_near : m;
}

// compute the two uint2 records {ya,ha},{yb,hb} for knots (2l, 2l+1) of one spline
__device__ __forceinline__ void spline_records(const float* __restrict__ src,
                                               int s, int lane,
                                               uint2& e0, uint2& e1) {
    float2 v = ((const float2*)(src + s * KNOTS))[lane];
    float y0 = v.x, y1 = v.y;                               // y[2l], y[2l+1]
    float y2 = __shfl_down_sync(0xFFFFFFFFu, y0, 1);        // y[2l+2]

    float da = (y1 - y0) * INV_H;                           // delta[2l]
    float db = (y2 - y1) * INV_H;                           // delta[2l+1]
    float dprev = __shfl_up_sync(0xFFFFFFFFu, db, 1);       // delta[2l-1]

    float m_e = (lane == 0)  ? pchip_endpoint(da, db)
                             : pchip_interior(dprev, da);
    float m_o = (lane == 31) ? pchip_endpoint(da, dprev)    // knot63: d62=da, d61=dprev
                             : pchip_interior(da, db);

    float he = H_VAL * m_e, ho = H_VAL * m_o;
    float he_next = __shfl_down_sync(0xFFFFFFFFu, he, 1);

    __half2 ya = __floats2half2_rn(y0, y1);
    __half2 ha = __floats2half2_rn(he, ho);
    __half2 yb = __floats2half2_rn(y1, (lane == 31) ? y1 : y2);
    __half2 hb = __floats2half2_rn(ho, (lane == 31) ? ho : he_next);

    e0.x = *reinterpret_cast<unsigned*>(&ya);
    e0.y = *reinterpret_cast<unsigned*>(&ha);
    e1.x = *reinterpret_cast<unsigned*>(&yb);
    e1.y = *reinterpret_cast<unsigned*>(&hb);
}

// ---------------------------------------------------------------------------
// Kernel A: PCHIP + pack, transposed layout. Block = one (din, dout-tile of 64),
// 512 threads. Warp w handles spline pairs (p, p+32) for p in {2w, 2w+1}, so
// each lane forms complete uint4 records. Staging pitch 33 uint4 (<=2-way store
// conflicts, conflict-free drain), drain is fully coalesced.
// ---------------------------------------------------------------------------
__global__ void __launch_bounds__(512) pchip_pack_kernel(const float* __restrict__ y) {
    __shared__ uint4 st[64 * 33];                  // [knot j][pair p], pitch 33

    const int tid  = threadIdx.x;
    const int w    = tid >> 5;
    const int lane = tid & 31;
    const int bx   = blockIdx.x;                   // din*4 + dx

    const float* src = y + (size_t)bx * 4096;      // 64 splines x 64 knots

#pragma unroll
    for (int k = 0; k < 2; ++k) {
        const int p = 2 * w + k;                   // pair index 0..31
        uint2 a0, a1, b0, b1;
        spline_records(src, p,      lane, a0, a1); // dout p
        spline_records(src, p + 32, lane, b0, b1); // dout p+32

        uint4 U0, U1;
        U0.x = a0.x; U0.y = a0.y; U0.z = b0.x; U0.w = b0.y;   // knot 2l
        U1.x = a1.x; U1.y = a1.y; U1.z = b1.x; U1.w = b1.y;   // knot 2l+1
        st[(2 * lane)     * 33 + p] = U0;
        st[(2 * lane + 1) * 33 + p] = U1;
    }
    __syncthreads();

    // drain: conflict-free smem reads, coalesced gmem stores
    uint4* dst = g_pack2 + (size_t)bx * TILE_U4;
#pragma unroll
    for (int g = tid; g < TILE_U4; g += 512) {
        int j = g >> 5, p = g & 31;
        dst[g] = st[j * 33 + p];
    }
}

// ---------------------------------------------------------------------------
// Kernel B: main gather-accumulate.
// Grid (4 dout tiles, 2 b tiles, 32 din chunks) = 256 blocks, 256 threads.
// Warp w owns b rows [w*32, w*32+32); lane l owns douts l and l+32 (local).
// Per (b,din): 1 broadcast LDS.128 (weights+idx) + 1 gather LDS.128 (both rows).
// ---------------------------------------------------------------------------
__device__ __forceinline__ void cp_async16(void* dst, const void* src) {
    unsigned sa = (unsigned)__cvta_generic_to_shared(dst);
    asm volatile("cp.async.cg.shared.global [%0], [%1], 16;\n" :: "r"(sa), "l"(src));
}
__device__ __forceinline__ __half2 u2h(unsigned u) {
    return *reinterpret_cast<__half2*>(&u);
}

__global__ void __launch_bounds__(256, 2) kan_main_kernel(const float* __restrict__ x) {
    extern __shared__ uint4 sm4[];
    uint4* tile = sm4;                       // 2 x TILE_U4
    uint4* cw   = sm4 + 2 * TILE_U4;         // TB*DCHUNK: {wy, wh, idx, 0}

    const int dx  = blockIdx.x;   // dout tile (0..3)
    const int by  = blockIdx.y;   // b tile    (0..1)
    const int ch  = blockIdx.z;   // din chunk (0..31)
    const int tid = threadIdx.x;

    // ---- hermite weights + idx, combined 16B records ----
    for (int i = tid; i < TB * DCHUNK; i += 256) {
        int bb = i >> 3, dl = i & 7;
        float xv = x[(by * TB + bb) * D_IN + ch * DCHUNK + dl];
        xv = fminf(fmaxf(xv, -2.0f), 2.0f);
        float tt = (xv + 2.0f) * INV_H;
        int idx = (int)floorf(tt);
        if (idx > KNOTS - 2) idx = KNOTS - 2;
        if (idx < 0) idx = 0;
        float u  = tt - (float)idx;
        float u2 = u * u, u3 = u2 * u;
        float h00 = 2.0f * u3 - 3.0f * u2 + 1.0f;
        float h10 = u3 - 2.0f * u2 + u;
        float h01 = 3.0f * u2 - 2.0f * u3;
        float h11 = u3 - u2;
        __half2 wy = __floats2half2_rn(h00, h01);
        __half2 wh = __floats2half2_rn(h10, h11);
        uint4 r;
        r.x = *reinterpret_cast<unsigned*>(&wy);
        r.y = *reinterpret_cast<unsigned*>(&wh);
        r.z = (unsigned)idx;
        r.w = 0;
        cw[i] = r;
    }

    const int w = tid >> 5, l = tid & 31;
    float acc0[32], acc1[32];
#pragma unroll
    for (int bb = 0; bb < 32; ++bb) { acc0[bb] = 0.0f; acc1[bb] = 0.0f; }

    auto issue_copy = [&](int d, int st) {
        const uint4* src = g_pack2 + ((size_t)(ch * DCHUNK + d) * 4 + dx) * TILE_U4;
        uint4* dst = tile + st * TILE_U4;
#pragma unroll
        for (int j = tid; j < TILE_U4; j += 256) cp_async16(dst + j, src + j);
    };

    issue_copy(0, 0);
    asm volatile("cp.async.commit_group;\n" ::: "memory");

    for (int d = 0; d < DCHUNK; ++d) {
        const int st = d & 1;
        if (d < DCHUNK - 1) {
            issue_copy(d + 1, st ^ 1);
            asm volatile("cp.async.commit_group;\n" ::: "memory");
            asm volatile("cp.async.wait_group 1;\n" ::: "memory");
        } else {
            asm volatile("cp.async.wait_group 0;\n" ::: "memory");
        }
        __syncthreads();

        const uint4* tl = tile + st * TILE_U4 + l;     // + idx*32 per gather
        const int base = (w * 32) * DCHUNK + d;

#pragma unroll
        for (int bb = 0; bb < 32; ++bb) {
            uint4 r = cw[base + bb * DCHUNK];          // broadcast LDS.128
            __half2 wy = u2h(r.x), wh = u2h(r.y);
            uint4 g = tl[(int)r.z * 32];               // gather LDS.128 (both rows)

            __half2 p0 = __hfma2(wh, u2h(g.y), __hmul2(wy, u2h(g.x)));
            __half2 p1 = __hfma2(wh, u2h(g.w), __hmul2(wy, u2h(g.z)));

            acc0[bb] += __half2float(__hadd(__low2half(p0), __high2half(p0)));
            acc1[bb] += __half2float(__hadd(__low2half(p1), __high2half(p1)));
        }
        __syncthreads();
    }

    // ---- write partials ----
    float* P = g_partial + ((size_t)ch * BATCH + by * TB + w * 32) * D_OUT + dx * 64;
#pragma unroll
    for (int bb = 0; bb < 32; ++bb) {
        P[bb * D_OUT + l]      = acc0[bb];
        P[bb * D_OUT + l + 32] = acc1[bb];
    }
}

// ---------------------------------------------------------------------------
// Kernel C: reduce 32 partials + bias
// ---------------------------------------------------------------------------
__global__ void __launch_bounds__(256) reduce_kernel(
        const float* __restrict__ bias, float* __restrict__ out) {
    int i = blockIdx.x * 256 + threadIdx.x;            // float4 index
    const float4* P = (const float4*)g_partial;
    float4 s = ((const float4*)bias)[i & 63];
#pragma unroll
    for (int c = 0; c < NCHUNK; ++c) {
        float4 p = P[(size_t)c * (BATCH * D_OUT / 4) + i];
        s.x += p.x; s.y += p.y; s.z += p.z; s.w += p.w;
    }
    ((float4*)out)[i] = s;
}

// ---------------------------------------------------------------------------
extern "C" void kernel_launch(void* const* d_in, const int* in_sizes, int n_in,
                              void* d_out, int out_size) {
    const float* x    = (const float*)d_in[0];
    const float* y    = (const float*)d_in[1];
    const float* bias = (const float*)d_in[2];
    float* out = (float*)d_out;

    cudaFuncSetAttribute(kan_main_kernel,
                         cudaFuncAttributeMaxDynamicSharedMemorySize, SMEM_BYTES);

    pchip_pack_kernel<<<D_IN * 4, 512>>>(y);
    kan_main_kernel<<<dim3(4, 2, NCHUNK), 256, SMEM_BYTES>>>(x);
    reduce_kernel<<<(BATCH * D_OUT / 4) / 256, 256>>>(bias, out);
}

// round 6
// speedup vs baseline: 1.1174x; 1.0617x over previous
#include <cuda_runtime.h>
#include <cuda_fp16.h>
#include <cstdint>

// Problem constants
#define D_IN   256
#define D_OUT  256
#define BATCH  512
#define KNOTS  64
#define INV_H  15.75f          // 63/4, exact in fp32
#define H_VAL  (4.0f/63.0f)

#define NCHUNK 32              // din chunks
#define DCHUNK 8               // din per chunk
#define TB     256             // batch rows per block

// B tile: 64 knots x 32 douts of uint2 {y2, hm2} = 16KB
#define TILE_U2 (64*32)        // 2048

// B smem: 2 tiles (32KB) + cw2 (2048*8=16KB) + cidx (2048*4=8KB) = 56KB
#define SMEM_BYTES ((2*TILE_U2 + 2048)*8 + 2048*4)

// Scratch (device globals; no allocation)
// g_pack[(g*64 + j)*32 + p], g = din*8 + dxt, p = dout%32:
//   uint2 { half2(y_j, y_j+1), half2(hm_j, hm_j+1) }
__device__ uint2 g_pack[(size_t)D_IN * D_OUT * KNOTS];          // 33.5 MB
__device__ float g_partial[(size_t)NCHUNK * BATCH * D_OUT];     // 16 MB

// ---------------------------------------------------------------------------
// PCHIP slope helpers (branch-free)
// ---------------------------------------------------------------------------
__device__ __forceinline__ float pchip_interior(float d0, float d1) {
    float p   = d0 * d1;
    float den = d0 + d1;
    float m   = __fdividef(2.0f * p, den);
    bool  ok  = (p > 0.0f) && (fabsf(den) >= 1e-12f);
    return ok ? m : 0.0f;
}
__device__ __forceinline__ float pchip_endpoint(float d_near, float d_far) {
    float m = 1.5f * d_near - 0.5f * d_far;
    m = (m * d_near <= 0.0f) ? 0.0f : m;
    bool clamp3 = (d_near * d_far < 0.0f) && (fabsf(m) > 3.0f * fabsf(d_near));
    return clamp3 ? 3.0f * d_near : m;
}

// ---------------------------------------------------------------------------
// Kernel A: PCHIP + pack, lane-parallel, no shuffles.
// Block = one group g of 32 splines (= one B tile column set). 512 threads.
// Thread (p = tid&31 spline, jb = (tid>>5)*4 knots) computes records jb..jb+3
// independently from an smem copy of y, stores coalesced to the B-ready layout.
// ---------------------------------------------------------------------------
__global__ void __launch_bounds__(512) pchip_pack_kernel(const float* __restrict__ y) {
    __shared__ float sy[32 * 67];                  // [spline p][knot], pitch 67

    const int t = threadIdx.x;
    const int g = blockIdx.x;                      // group = din*8 + dxt
    const float* src = y + (size_t)g * 2048;       // 32 splines x 64 knots

    // stage 8KB coalesced
    {
        float4 v = ((const float4*)src)[t];        // word offset 4t
        int p  = t >> 4;                           // (4t)/64
        int j0 = (t & 15) << 2;
        float* r = sy + p * 67 + j0;
        r[0] = v.x; r[1] = v.y; r[2] = v.z; r[3] = v.w;
    }
    __syncthreads();

    const int p  = t & 31;                         // spline (lane)
    const int jb = (t >> 5) << 2;                  // knot base 0..60 (uniform per warp)
    const float* row = sy + p * 67;

    // local y window y[jb-1 .. jb+5], clamped
    float ly[7];
#pragma unroll
    for (int k = 0; k < 7; ++k) {
        int j = jb - 1 + k;
        j = j < 0 ? 0 : (j > 63 ? 63 : j);
        ly[k] = row[j];
    }

    // deltas d[k] = delta[jb-1+k]
    float d[6];
#pragma unroll
    for (int k = 0; k < 6; ++k) d[k] = (ly[k + 1] - ly[k]) * INV_H;

    // slopes at knots jb..jb+4 (interior), endpoints overwritten (uniform branch)
    float s[5];
#pragma unroll
    for (int k = 0; k < 5; ++k) s[k] = pchip_interior(d[k], d[k + 1]);
    if (jb == 0)  s[0] = pchip_endpoint(d[1], d[2]);   // m0: delta0=d[1], delta1=d[2]
    if (jb == 60) s[3] = pchip_endpoint(d[3], d[2]);   // m63: delta62=d[3], delta61=d[2]

    float hm[5];
#pragma unroll
    for (int k = 0; k < 5; ++k) hm[k] = H_VAL * s[k];

    // records jb..jb+3, coalesced stores (lanes p contiguous)
    uint2* dst = g_pack + ((size_t)g * 64 + jb) * 32 + p;
#pragma unroll
    for (int kk = 0; kk < 4; ++kk) {
        __half2 y2 = __floats2half2_rn(ly[kk + 1], ly[kk + 2]);
        __half2 h2 = __floats2half2_rn(hm[kk], hm[kk + 1]);
        uint2 rec;
        rec.x = *reinterpret_cast<unsigned*>(&y2);
        rec.y = *reinterpret_cast<unsigned*>(&h2);
        dst[kk * 32] = rec;
    }
}

// ---------------------------------------------------------------------------
// Kernel B: main gather-accumulate.
// Grid (8 dxt, 2 by, 32 ch) = 512 blocks, 256 threads, 4 blocks/SM.
// Warp w owns b rows [w*32, w*32+32); lane l owns dout dxt*32+l.
// Per (b,din): broadcast LDS.64+LDS.32 (weights,idx) + 1 gather LDS.64.
// ---------------------------------------------------------------------------
__device__ __forceinline__ void cp_async16(void* dst, const void* src) {
    unsigned sa = (unsigned)__cvta_generic_to_shared(dst);
    asm volatile("cp.async.cg.shared.global [%0], [%1], 16;\n" :: "r"(sa), "l"(src));
}
__device__ __forceinline__ __half2 u2h(unsigned u) {
    return *reinterpret_cast<__half2*>(&u);
}

__global__ void __launch_bounds__(256, 4) kan_main_kernel(const float* __restrict__ x) {
    extern __shared__ uint2 sm2[];
    uint2* tile = sm2;                        // 2 x TILE_U2
    uint2* cw2  = sm2 + 2 * TILE_U2;          // 2048: {wy, wh}
    int*   cidx = (int*)(cw2 + 2048);         // 2048: idx

    const int dxt = blockIdx.x;   // dout tile of 32 (0..7)
    const int by  = blockIdx.y;   // b tile    (0..1)
    const int ch  = blockIdx.z;   // din chunk (0..31)
    const int tid = threadIdx.x;

    // ---- hermite weights + idx ----
    for (int i = tid; i < TB * DCHUNK; i += 256) {
        int bb = i >> 3, dl = i & 7;
        float xv = x[(by * TB + bb) * D_IN + ch * DCHUNK + dl];
        xv = fminf(fmaxf(xv, -2.0f), 2.0f);
        float tt = (xv + 2.0f) * INV_H;
        int idx = (int)floorf(tt);
        if (idx > KNOTS - 2) idx = KNOTS - 2;
        if (idx < 0) idx = 0;
        float u  = tt - (float)idx;
        float u2 = u * u, u3 = u2 * u;
        float h00 = 2.0f * u3 - 3.0f * u2 + 1.0f;
        float h10 = u3 - 2.0f * u2 + u;
        float h01 = 3.0f * u2 - 2.0f * u3;
        float h11 = u3 - u2;
        __half2 wy = __floats2half2_rn(h00, h01);
        __half2 wh = __floats2half2_rn(h10, h11);
        uint2 r;
        r.x = *reinterpret_cast<unsigned*>(&wy);
        r.y = *reinterpret_cast<unsigned*>(&wh);
        cw2[i]  = r;
        cidx[i] = idx;
    }

    const int w = tid >> 5, l = tid & 31;
    float acc[32];
#pragma unroll
    for (int bb = 0; bb < 32; ++bb) acc[bb] = 0.0f;

    auto issue_copy = [&](int d, int st) {
        const uint2* src = g_pack + ((size_t)(ch * DCHUNK + d) * 8 + dxt) * TILE_U2;
        uint2* dst = tile + st * TILE_U2;
#pragma unroll
        for (int j = tid; j < TILE_U2 / 2; j += 256)
            cp_async16((char*)dst + j * 16, (const char*)src + j * 16);
    };

    issue_copy(0, 0);
    asm volatile("cp.async.commit_group;\n" ::: "memory");

    for (int d = 0; d < DCHUNK; ++d) {
        const int st = d & 1;
        if (d < DCHUNK - 1) {
            issue_copy(d + 1, st ^ 1);
            asm volatile("cp.async.commit_group;\n" ::: "memory");
            asm volatile("cp.async.wait_group 1;\n" ::: "memory");
        } else {
            asm volatile("cp.async.wait_group 0;\n" ::: "memory");
        }
        __syncthreads();

        const uint2* tl = tile + st * TILE_U2 + l;     // + idx*32 per gather
        const int base = (w * 32) * DCHUNK + d;

#pragma unroll
        for (int bb = 0; bb < 32; ++bb) {
            int   i = cidx[base + bb * DCHUNK];        // broadcast
            uint2 r = cw2 [base + bb * DCHUNK];        // broadcast LDS.64
            uint2 gr = tl[i * 32];                     // gather LDS.64 (conflict-free)

            __half2 p0 = __hfma2(u2h(r.y), u2h(gr.y), __hmul2(u2h(r.x), u2h(gr.x)));
            acc[bb] += __half2float(__hadd(__low2half(p0), __high2half(p0)));
        }
        __syncthreads();
    }

    // ---- write partials ----
    float* P = g_partial + ((size_t)ch * BATCH + by * TB + w * 32) * D_OUT + dxt * 32;
#pragma unroll
    for (int bb = 0; bb < 32; ++bb)
        P[bb * D_OUT + l] = acc[bb];
}

// ---------------------------------------------------------------------------
// Kernel C: reduce 32 partials + bias
// ---------------------------------------------------------------------------
__global__ void __launch_bounds__(256) reduce_kernel(
        const float* __restrict__ bias, float* __restrict__ out) {
    int i = blockIdx.x * 256 + threadIdx.x;            // float4 index
    const float4* P = (const float4*)g_partial;
    float4 s = ((const float4*)bias)[i & 63];
#pragma unroll
    for (int c = 0; c < NCHUNK; ++c) {
        float4 p = P[(size_t)c * (BATCH * D_OUT / 4) + i];
        s.x += p.x; s.y += p.y; s.z += p.z; s.w += p.w;
    }
    ((float4*)out)[i] = s;
}

// ---------------------------------------------------------------------------
extern "C" void kernel_launch(void* const* d_in, const int* in_sizes, int n_in,
                              void* d_out, int out_size) {
    const float* x    = (const float*)d_in[0];
    const float* y    = (const float*)d_in[1];
    const float* bias = (const float*)d_in[2];
    float* out = (float*)d_out;

    cudaFuncSetAttribute(kan_main_kernel,
                         cudaFuncAttributeMaxDynamicSharedMemorySize, SMEM_BYTES);

    pchip_pack_kernel<<<D_IN * 8, 512>>>(y);
    kan_main_kernel<<<dim3(8, 2, NCHUNK), 256, SMEM_BYTES>>>(x);
    reduce_kernel<<<(BATCH * D_OUT / 4) / 256, 256>>>(bias, out);
}

// round 7
// speedup vs baseline: 1.1920x; 1.0667x over previous
#include <cuda_runtime.h>
#include <cuda_fp16.h>
#include <cstdint>

// Problem constants
#define D_IN   256
#define D_OUT  256
#define BATCH  512
#define KNOTS  64
#define INV_H  15.75f          // 63/4, exact in fp32
#define H_VAL  (4.0f/63.0f)

#define NCHUNK 32              // din chunks
#define DCHUNK 8               // din per chunk
#define TB     256             // batch rows per block

// B tile: 64 knots x 32 pairs of uint4 {y2(p), hm2(p), y2(p+32), hm2(p+32)} = 32KB
#define TILE_U4 (64*32)        // 2048 uint4

// B smem: 2 tiles (64KB) + cw (2048 uint4 = 32KB) = 96KB
#define SMEM_BYTES ((2*TILE_U4 + 2048)*16)

// Scratch (device globals; no allocation)
// g_pack2[(din*4+dxt)*2048 + j*32 + p] = {y2(p,j), hm2(p,j), y2(p+32,j), hm2(p+32,j)}
__device__ uint4 g_pack2[(size_t)D_IN * 4 * TILE_U4];           // 33.5 MB
__device__ float g_partial[(size_t)NCHUNK * BATCH * D_OUT];     // 16 MB

// ---------------------------------------------------------------------------
// PCHIP helpers (branch-free)
// ---------------------------------------------------------------------------
__device__ __forceinline__ float pchip_interior(float d0, float d1) {
    float p   = d0 * d1;
    float den = d0 + d1;
    float m   = __fdividef(2.0f * p, den);
    bool  ok  = (p > 0.0f) && (fabsf(den) >= 1e-12f);
    return ok ? m : 0.0f;
}
__device__ __forceinline__ float pchip_endpoint(float d_near, float d_far) {
    float m = 1.5f * d_near - 0.5f * d_far;
    m = (m * d_near <= 0.0f) ? 0.0f : m;
    bool clamp3 = (d_near * d_far < 0.0f) && (fabsf(m) > 3.0f * fabsf(d_near));
    return clamp3 ? 3.0f * d_near : m;
}

// 4 records (knots jb..jb+3) for one spline. rowd points at y[jb] in smem
// (data stored at offset +1 within a 67-float pitch row, so rowd[-1] is valid
// memory: the pad slot for jb==0, or y[jb-1] otherwise).
__device__ __forceinline__ void spline4(const float* __restrict__ rowd, int jb,
                                        unsigned y2[4], unsigned h2[4]) {
    float ly[7];
#pragma unroll
    for (int k = 0; k < 7; ++k) ly[k] = rowd[k - 1];   // y[jb-1 .. jb+5]

    float d[6];
#pragma unroll
    for (int k = 0; k < 6; ++k) d[k] = (ly[k + 1] - ly[k]) * INV_H;

    float s[5];
#pragma unroll
    for (int k = 0; k < 5; ++k) s[k] = pchip_interior(d[k], d[k + 1]);
    if (jb == 0)  s[0] = pchip_endpoint(d[1], d[2]);   // m0 (pad in d[0] discarded)
    if (jb == 60) s[3] = pchip_endpoint(d[3], d[2]);   // m63 (pad in d[4],d[5] only
                                                       // reaches record 63, never gathered)
#pragma unroll
    for (int kk = 0; kk < 4; ++kk) {
        __half2 yv = __floats2half2_rn(ly[kk + 1], ly[kk + 2]);
        __half2 hv = __floats2half2_rn(H_VAL * s[kk], H_VAL * s[kk + 1]);
        y2[kk] = *reinterpret_cast<unsigned*>(&yv);
        h2[kk] = *reinterpret_cast<unsigned*>(&hv);
    }
}

// ---------------------------------------------------------------------------
// Kernel A: PCHIP + pack. Block = 64 splines (one dout-tile group), 512 thr.
// Thread (p = t&31, jb = (t>>5)*4) handles splines p and p+32, emitting 4
// complete uint4 records with coalesced STG.128.
// ---------------------------------------------------------------------------
__global__ void __launch_bounds__(512) pchip_pack_kernel(const float* __restrict__ y) {
    __shared__ float sy[64 * 67];                  // [spline][1 + knot], pitch 67

    const int t  = threadIdx.x;
    const int bx = blockIdx.x;                     // din*4 + dxt
    const float* src = y + (size_t)bx * 4096;      // 64 splines x 64 knots

    // stage 16KB coalesced (8 floats per thread)
    {
        float4 v0 = ((const float4*)src)[2 * t];
        float4 v1 = ((const float4*)src)[2 * t + 1];
        int p  = t >> 3;
        int j0 = (t & 7) << 3;
        float* r = sy + p * 67 + 1 + j0;
        r[0] = v0.x; r[1] = v0.y; r[2] = v0.z; r[3] = v0.w;
        r[4] = v1.x; r[5] = v1.y; r[6] = v1.z; r[7] = v1.w;
    }
    __syncthreads();

    const int p  = t & 31;
    const int jb = (t >> 5) << 2;                  // 0..60, uniform per warp

    unsigned ya[4], hA[4], yb[4], hB[4];
    spline4(sy + p * 67 + 1 + jb,        jb, ya, hA);   // spline p
    spline4(sy + (p + 32) * 67 + 1 + jb, jb, yb, hB);   // spline p+32

    uint4* dst = g_pack2 + (size_t)bx * TILE_U4 + jb * 32 + p;
#pragma unroll
    for (int kk = 0; kk < 4; ++kk) {
        uint4 rec;
        rec.x = ya[kk]; rec.y = hA[kk]; rec.z = yb[kk]; rec.w = hB[kk];
        dst[kk * 32] = rec;                        // lanes p contiguous: coalesced
    }
}

// ---------------------------------------------------------------------------
// Kernel B: main gather-accumulate.
// Grid (4 dxt, 2 by, 32 ch) = 256 blocks, 256 threads, 2 blocks/SM.
// Warp w owns b rows [w*32, w*32+32); lane l owns douts l and l+32 (local).
// Per (b,din): broadcast LDS.128 {wy,wh,byteoff} + one gather LDS.128.
// ---------------------------------------------------------------------------
__device__ __forceinline__ void cp_async16(void* dst, const void* src) {
    unsigned sa = (unsigned)__cvta_generic_to_shared(dst);
    asm volatile("cp.async.cg.shared.global [%0], [%1], 16;\n" :: "r"(sa), "l"(src));
}
__device__ __forceinline__ __half2 u2h(unsigned u) {
    return *reinterpret_cast<__half2*>(&u);
}

__global__ void __launch_bounds__(256, 2) kan_main_kernel(const float* __restrict__ x) {
    extern __shared__ uint4 sm4[];
    uint4* tile = sm4;                       // 2 x TILE_U4
    uint4* cw   = sm4 + 2 * TILE_U4;         // 2048: {wy, wh, byteoff, 0}

    const int dx  = blockIdx.x;   // dout tile of 64 (0..3)
    const int by  = blockIdx.y;   // b tile (0..1)
    const int ch  = blockIdx.z;   // din chunk (0..31)
    const int tid = threadIdx.x;

    // ---- hermite weights + gather byte offset ----
    for (int i = tid; i < TB * DCHUNK; i += 256) {
        int bb = i >> 3, dl = i & 7;
        float xv = x[(by * TB + bb) * D_IN + ch * DCHUNK + dl];
        xv = fminf(fmaxf(xv, -2.0f), 2.0f);
        float tt = (xv + 2.0f) * INV_H;
        int idx = (int)floorf(tt);
        if (idx > KNOTS - 2) idx = KNOTS - 2;
        if (idx < 0) idx = 0;
        float u  = tt - (float)idx;
        float u2 = u * u, u3 = u2 * u;
        float h00 = 2.0f * u3 - 3.0f * u2 + 1.0f;
        float h10 = u3 - 2.0f * u2 + u;
        float h01 = 3.0f * u2 - 2.0f * u3;
        float h11 = u3 - u2;
        __half2 wy = __floats2half2_rn(h00, h01);
        __half2 wh = __floats2half2_rn(h10, h11);
        uint4 r;
        r.x = *reinterpret_cast<unsigned*>(&wy);
        r.y = *reinterpret_cast<unsigned*>(&wh);
        r.z = (unsigned)(idx << 9);          // idx * 512B (record row = 32 uint4)
        r.w = 0;
        cw[i] = r;
    }

    const int w = tid >> 5, l = tid & 31;
    float acc0[32], acc1[32];
#pragma unroll
    for (int bb = 0; bb < 32; ++bb) { acc0[bb] = 0.0f; acc1[bb] = 0.0f; }

    auto issue_copy = [&](int d, int st) {
        const uint4* src = g_pack2 + ((size_t)(ch * DCHUNK + d) * 4 + dx) * TILE_U4;
        uint4* dst = tile + st * TILE_U4;
#pragma unroll
        for (int j = tid; j < TILE_U4; j += 256) cp_async16(dst + j, src + j);
    };

    issue_copy(0, 0);
    asm volatile("cp.async.commit_group;\n" ::: "memory");

    for (int d = 0; d < DCHUNK; ++d) {
        const int st = d & 1;
        if (d < DCHUNK - 1) {
            issue_copy(d + 1, st ^ 1);
            asm volatile("cp.async.commit_group;\n" ::: "memory");
            asm volatile("cp.async.wait_group 1;\n" ::: "memory");
        } else {
            asm volatile("cp.async.wait_group 0;\n" ::: "memory");
        }
        __syncthreads();

        const char* tb = (const char*)(tile + st * TILE_U4) + (l << 4);
        const int base = (w * 32) * DCHUNK + d;

#pragma unroll
        for (int bb = 0; bb < 32; ++bb) {
            uint4 r = cw[base + bb * DCHUNK];              // broadcast LDS.128
            uint4 g = *(const uint4*)(tb + r.z);           // gather LDS.128

            __half2 p0 = __hfma2(u2h(r.y), u2h(g.y), __hmul2(u2h(r.x), u2h(g.x)));
            __half2 p1 = __hfma2(u2h(r.y), u2h(g.w), __hmul2(u2h(r.x), u2h(g.z)));

            acc0[bb] += __half2float(__hadd(__low2half(p0), __high2half(p0)));
            acc1[bb] += __half2float(__hadd(__low2half(p1), __high2half(p1)));
        }
        __syncthreads();
    }

    // ---- write partials ----
    float* P = g_partial + ((size_t)ch * BATCH + by * TB + w * 32) * D_OUT + dx * 64;
#pragma unroll
    for (int bb = 0; bb < 32; ++bb) {
        P[bb * D_OUT + l]      = acc0[bb];
        P[bb * D_OUT + l + 32] = acc1[bb];
    }
}

// ---------------------------------------------------------------------------
// Kernel C: reduce 32 partials + bias
// ---------------------------------------------------------------------------
__global__ void __launch_bounds__(256) reduce_kernel(
        const float* __restrict__ bias, float* __restrict__ out) {
    int i = blockIdx.x * 256 + threadIdx.x;            // float4 index
    const float4* P = (const float4*)g_partial;
    float4 s = ((const float4*)bias)[i & 63];
#pragma unroll
    for (int c = 0; c < NCHUNK; ++c) {
        float4 p = P[(size_t)c * (BATCH * D_OUT / 4) + i];
        s.x += p.x; s.y += p.y; s.z += p.z; s.w += p.w;
    }
    ((float4*)out)[i] = s;
}

// ---------------------------------------------------------------------------
extern "C" void kernel_launch(void* const* d_in, const int* in_sizes, int n_in,
                              void* d_out, int out_size) {
    const float* x    = (const float*)d_in[0];
    const float* y    = (const float*)d_in[1];
    const float* bias = (const float*)d_in[2];
    float* out = (float*)d_out;

    cudaFuncSetAttribute(kan_main_kernel,
                         cudaFuncAttributeMaxDynamicSharedMemorySize, SMEM_BYTES);

    pchip_pack_kernel<<<D_IN * 4, 512>>>(y);
    kan_main_kernel<<<dim3(4, 2, NCHUNK), 256, SMEM_BYTES>>>(x);
    reduce_kernel<<<(BATCH * D_OUT / 4) / 256, 256>>>(bias, out);
}